// round 8
// baseline (speedup 1.0000x reference)
#include <cuda_runtime.h>
#include <math.h>
#include <stdint.h>

#define HH 128
#define WW 128
#define BB 8
#define CIN 64
#define COUT 64
#define HW (HH*WW)
#define NCH 27            // 18 offset channels + 9 mask channels
#define CST 66            // colT row stride in u64 (16B aligned, even)

// scratch (allocation-free: device globals)
__device__ float g_om[BB*NCH*HW];     // offsets + mask=2*sigmoid
__device__ float g_wT[9*64*64];       // [tap][cin][oc]

// ---------------------------------------------------------------------------
// packed fp32x2 helpers
// ---------------------------------------------------------------------------
__device__ __forceinline__ uint64_t pack2(float lo, float hi) {
    uint64_t r;
    asm("mov.b64 %0, {%1,%2};" : "=l"(r)
        : "r"(__float_as_uint(lo)), "r"(__float_as_uint(hi)));
    return r;
}
__device__ __forceinline__ void unpack2(uint64_t v, float& lo, float& hi) {
    uint32_t a, b;
    asm("mov.b64 {%0,%1}, %2;" : "=r"(a), "=r"(b) : "l"(v));
    lo = __uint_as_float(a); hi = __uint_as_float(b);
}
#define FFMA2(acc, a, b) \
    asm("fma.rn.f32x2 %0, %1, %2, %0;" : "+l"(acc) : "l"(a), "l"(b))

// ---------------------------------------------------------------------------
// Kernel 0: weight transform [oc][c][3][3] -> g_wT[t][c][oc]
// ---------------------------------------------------------------------------
__global__ void transpose_w_kernel(const float* __restrict__ w) {
    int idx = blockIdx.x * 256 + threadIdx.x;
    if (idx < 576 * COUT) {
        int oc  = idx / 576;
        int rem = idx % 576;
        int c   = rem / 9;
        int t   = rem % 9;
        g_wT[t * 4096 + c * 64 + oc] = w[idx];
    }
}

// ---------------------------------------------------------------------------
// Kernel 1: fused 3x3 conv -> 18 offsets + 9 masks (2*sigmoid).
// oc-pairs split across blockIdx.z. 2 output rows per block. grid=(H/2,B,2).
// (unchanged from R7: measured 105.9us)
// ---------------------------------------------------------------------------
#define NPAIR 7

__global__ void __launch_bounds__(128, 5) conv_offmask_kernel(
    const float* __restrict__ data,
    const float* __restrict__ w_off, const float* __restrict__ b_off,
    const float* __restrict__ w_mod, const float* __restrict__ b_mod)
{
    __shared__ uint64_t wsp[NPAIR * 32 * 10];       // 17920 B
    __shared__ float    dtile[8 * 4 * 132];         // 16896 B

    const int h0 = blockIdx.x * 2;
    const int b  = blockIdx.y;
    const int pb = blockIdx.z * NPAIR;              // pair base (0 or 7)
    const int x  = threadIdx.x;

    if (threadIdx.x < 64) {
        int q = threadIdx.x >> 3;
        int r = (threadIdx.x >> 1) & 3;
        int s = threadIdx.x & 1;
        dtile[q * 528 + r * 132 + s * 129] = 0.0f;
    }

    uint64_t acc2[2][NPAIR];
#pragma unroll
    for (int p = 0; p < NPAIR; p++) {
        int ocA = 2 * (pb + p), ocB = ocA + 1;
        float bA = (ocA < 18) ? b_off[ocA] : b_mod[ocA - 18];
        float bB = (ocB < 18) ? b_off[ocB] : ((ocB < 27) ? b_mod[ocB - 18] : 0.0f);
        acc2[0][p] = pack2(bA, bB);
        acc2[1][p] = acc2[0][p];
    }

    for (int c0 = 0; c0 < CIN; c0 += 32) {
        __syncthreads();
        for (int idx = threadIdx.x; idx < NPAIR * 32 * 9; idx += 128) {
            int p  = idx / 288;
            int r  = idx % 288;
            int cc = r / 9;
            int k  = r % 9;
            int ocA = 2 * (pb + p), ocB = ocA + 1;
            const float* sA = (ocA < 18) ? (w_off + ocA * 576) : (w_mod + (ocA - 18) * 576);
            float vA = sA[(c0 + cc) * 9 + k];
            float vB = 0.0f;
            if (ocB < 27) {
                const float* sB = (ocB < 18) ? (w_off + ocB * 576) : (w_mod + (ocB - 18) * 576);
                vB = sB[(c0 + cc) * 9 + k];
            }
            wsp[(p * 32 + cc) * 10 + k] = pack2(vA, vB);
        }

        for (int cg = 0; cg < 4; cg++) {
            __syncthreads();
            const int cb = c0 + cg * 8;
#pragma unroll
            for (int q = 0; q < 8; q++) {
                const float* dp = data + ((size_t)(b * CIN + cb + q)) * HW;
#pragma unroll
                for (int r = 0; r < 4; r++) {
                    int hy = h0 - 1 + r;
                    float v = 0.0f;
                    if (hy >= 0 && hy < HH) v = dp[hy * WW + x];
                    dtile[q * 528 + r * 132 + 1 + x] = v;
                }
            }
            __syncthreads();

#pragma unroll
            for (int q = 0; q < 8; q++) {
                const int cc = cg * 8 + q;
                const float* dp = dtile + q * 528 + x;
                uint64_t dup[4][3];
#pragma unroll
                for (int r = 0; r < 4; r++)
#pragma unroll
                    for (int kx = 0; kx < 3; kx++) {
                        float v = dp[r * 132 + kx];
                        dup[r][kx] = pack2(v, v);
                    }

#pragma unroll
                for (int p = 0; p < NPAIR; p++) {
                    const uint64_t* base = wsp + (p * 32 + cc) * 10;
                    ulonglong2 w01 = *(const ulonglong2*)(base + 0);
                    ulonglong2 w23 = *(const ulonglong2*)(base + 2);
                    ulonglong2 w45 = *(const ulonglong2*)(base + 4);
                    ulonglong2 w67 = *(const ulonglong2*)(base + 6);
                    uint64_t   w8  = base[8];
                    FFMA2(acc2[0][p], dup[0][0], w01.x);
                    FFMA2(acc2[0][p], dup[0][1], w01.y);
                    FFMA2(acc2[0][p], dup[0][2], w23.x);
                    FFMA2(acc2[0][p], dup[1][0], w23.y);
                    FFMA2(acc2[0][p], dup[1][1], w45.x);
                    FFMA2(acc2[0][p], dup[1][2], w45.y);
                    FFMA2(acc2[0][p], dup[2][0], w67.x);
                    FFMA2(acc2[0][p], dup[2][1], w67.y);
                    FFMA2(acc2[0][p], dup[2][2], w8);
                    FFMA2(acc2[1][p], dup[1][0], w01.x);
                    FFMA2(acc2[1][p], dup[1][1], w01.y);
                    FFMA2(acc2[1][p], dup[1][2], w23.x);
                    FFMA2(acc2[1][p], dup[2][0], w23.y);
                    FFMA2(acc2[1][p], dup[2][1], w45.x);
                    FFMA2(acc2[1][p], dup[2][2], w45.y);
                    FFMA2(acc2[1][p], dup[3][0], w67.x);
                    FFMA2(acc2[1][p], dup[3][1], w67.y);
                    FFMA2(acc2[1][p], dup[3][2], w8);
                }
            }
        }
    }

#pragma unroll
    for (int rr = 0; rr < 2; rr++) {
        float* outp = g_om + ((size_t)(b * NCH) * HH + (h0 + rr)) * WW + x;
#pragma unroll
        for (int p = 0; p < NPAIR; p++) {
            float lo, hi;
            unpack2(acc2[rr][p], lo, hi);
            int ocA = 2 * (pb + p), ocB = ocA + 1;
            if (ocA >= 18) lo = 2.0f / (1.0f + expf(-lo));
            outp[ocA * HW] = lo;
            if (ocB < 27) {
                if (ocB >= 18) hi = 2.0f / (1.0f + expf(-hi));
                outp[ocB * HW] = hi;
            }
        }
    }
}

// ---------------------------------------------------------------------------
// Kernel 2: deform sample + GEMM (simple tap-chunked structure, R4-style),
// with pre-duplicated u64 colT (no pack MOVs in the GEMM inner loop) and a
// warp-friendly oc/px thread mapping.
// block = 128 threads, 64 px, 64 oc. smem 49.8KB -> 4 blocks/SM.
// grid = (W/64, H, B)
// ---------------------------------------------------------------------------
__global__ void __launch_bounds__(128, 4) deform_main_kernel(
    const float* __restrict__ data,
    const float* __restrict__ bias,
    float* __restrict__ out)
{
    __shared__ float    wsm[4096];        // [cin][oc] for current tap (16KB)
    __shared__ uint64_t colT[64 * CST];   // [cin][px] dup pairs (33.8KB)

    const int w0  = blockIdx.x * 64;
    const int h   = blockIdx.y;
    const int b   = blockIdx.z;
    const int tid = threadIdx.x;

    const float* dbase = data + (size_t)b * CIN * HW;
    const float* omb   = g_om + ((size_t)(b * NCH) * HH + h) * WW;

    // GEMM mapping: warp spans 8 oc-groups x 4 px-groups
    const int oc0 = (tid & 7) * 8;       // oc base
    const int j   = tid >> 3;            // 0..15 -> px base j*4

    // gather mapping: pixel gp, channel half gc
    const int gp = tid & 63;
    const int gc = (tid >> 6) * 32;
    const int x  = w0 + gp;

    uint64_t acc[4][4];                  // [oc pair][px]
#pragma unroll
    for (int p = 0; p < 4; p++)
#pragma unroll
        for (int q = 0; q < 4; q++) acc[p][q] = 0ULL;

    for (int t = 0; t < 9; t++) {
        if (t) __syncthreads();          // prev GEMM done before overwrite

        // stage this tap's weights (16KB, float4)
        {
            const float4* bsrc = (const float4*)(g_wT + t * 4096);
            float4* bdst = (float4*)wsm;
#pragma unroll
            for (int r = 0; r < 8; r++) bdst[tid + r * 128] = bsrc[tid + r * 128];
        }

        // bilinear metadata for this thread's pixel (inline)
        const float dy = omb[(2 * t) * HW + x];
        const float dx = omb[(2 * t + 1) * HW + x];
        const float mk = omb[(18 + t) * HW + x];

        const float py = (float)(h - 1 + t / 3) + dy;
        const float px = (float)(x - 1 + t % 3) + dx;

        const float y0f = floorf(py), x0f = floorf(px);
        const float wy1 = py - y0f,  wx1 = px - x0f;
        const float wy0 = 1.0f - wy1, wx0 = 1.0f - wx1;

        const int y0 = (int)y0f, x0 = (int)x0f;
        const int y1 = y0 + 1,   x1 = x0 + 1;
        const bool vy0 = (y0 >= 0) && (y0 < HH);
        const bool vy1 = (y1 >= 0) && (y1 < HH);
        const bool vx0 = (x0 >= 0) && (x0 < WW);
        const bool vx1 = (x1 >= 0) && (x1 < WW);

        const float w00 = (vy0 && vx0) ? mk * wy0 * wx0 : 0.0f;
        const float w01 = (vy0 && vx1) ? mk * wy0 * wx1 : 0.0f;
        const float w10 = (vy1 && vx0) ? mk * wy1 * wx0 : 0.0f;
        const float w11 = (vy1 && vx1) ? mk * wy1 * wx1 : 0.0f;

        const int yc0 = min(max(y0, 0), HH - 1);
        const int yc1 = min(max(y1, 0), HH - 1);
        const int xc0 = min(max(x0, 0), WW - 1);
        const int xc1 = min(max(x1, 0), WW - 1);
        const int i00 = yc0 * WW + xc0;
        const int i01 = yc0 * WW + xc1;
        const int i10 = yc1 * WW + xc0;
        const int i11 = yc1 * WW + xc1;

        // gather 32 channels for this pixel; store dup pairs
        const float* d2 = dbase + (size_t)gc * HW;
        uint64_t* cp = colT + gc * CST + gp;
#pragma unroll 8
        for (int cc = 0; cc < 32; cc++) {
            float v = w00 * d2[i00];
            v = fmaf(w01, d2[i01], v);
            v = fmaf(w10, d2[i10], v);
            v = fmaf(w11, d2[i11], v);
            cp[cc * CST] = pack2(v, v);
            d2 += HW;
        }
        __syncthreads();

        // GEMM: 64 k for this tap, no packing in the loop
        const float*    wrow = wsm + oc0;
        const uint64_t* crow = colT + j * 4;
#pragma unroll 8
        for (int kl = 0; kl < 64; kl++) {
            ulonglong2 wA = *(const ulonglong2*)(wrow + kl * 64);      // oc 0-3
            ulonglong2 wB = *(const ulonglong2*)(wrow + kl * 64 + 4);  // oc 4-7
            ulonglong2 ca = *(const ulonglong2*)(crow + kl * CST);     // px 0,1
            ulonglong2 cb = *(const ulonglong2*)(crow + kl * CST + 2); // px 2,3
            FFMA2(acc[0][0], wA.x, ca.x); FFMA2(acc[0][1], wA.x, ca.y);
            FFMA2(acc[0][2], wA.x, cb.x); FFMA2(acc[0][3], wA.x, cb.y);
            FFMA2(acc[1][0], wA.y, ca.x); FFMA2(acc[1][1], wA.y, ca.y);
            FFMA2(acc[1][2], wA.y, cb.x); FFMA2(acc[1][3], wA.y, cb.y);
            FFMA2(acc[2][0], wB.x, ca.x); FFMA2(acc[2][1], wB.x, ca.y);
            FFMA2(acc[2][2], wB.x, cb.x); FFMA2(acc[2][3], wB.x, cb.y);
            FFMA2(acc[3][0], wB.y, ca.x); FFMA2(acc[3][1], wB.y, ca.y);
            FFMA2(acc[3][2], wB.y, cb.x); FFMA2(acc[3][3], wB.y, cb.y);
        }
    }

    // ---- epilogue: bias + relu + float4 stores ----
#pragma unroll
    for (int p = 0; p < 4; p++) {
        const int ocA = oc0 + 2 * p;
        const float bA = bias[ocA];
        const float bB = bias[ocA + 1];
        float a0, b0, a1, b1, a2, b2, a3, b3;
        unpack2(acc[p][0], a0, b0);
        unpack2(acc[p][1], a1, b1);
        unpack2(acc[p][2], a2, b2);
        unpack2(acc[p][3], a3, b3);
        float* obA = out + (((size_t)(b * COUT + ocA)) * HH + h) * WW + w0 + j * 4;
        float4 rA = make_float4(fmaxf(a0 + bA, 0.f), fmaxf(a1 + bA, 0.f),
                                fmaxf(a2 + bA, 0.f), fmaxf(a3 + bA, 0.f));
        *(float4*)obA = rA;
        float4 rB = make_float4(fmaxf(b0 + bB, 0.f), fmaxf(b1 + bB, 0.f),
                                fmaxf(b2 + bB, 0.f), fmaxf(b3 + bB, 0.f));
        *(float4*)(obA + HW) = rB;
    }
}

// ---------------------------------------------------------------------------
extern "C" void kernel_launch(void* const* d_in, const int* in_sizes, int n_in,
                              void* d_out, int out_size)
{
    const float* data  = (const float*)d_in[0];
    const float* w     = (const float*)d_in[1];
    const float* bias  = (const float*)d_in[2];
    const float* w_off = (const float*)d_in[3];
    const float* b_off = (const float*)d_in[4];
    const float* w_mod = (const float*)d_in[5];
    const float* b_mod = (const float*)d_in[6];
    float* out = (float*)d_out;

    conv_offmask_kernel<<<dim3(HH / 2, BB, 2), 128>>>(data, w_off, b_off, w_mod, b_mod);
    transpose_w_kernel<<<144, 256>>>(w);
    deform_main_kernel<<<dim3(WW / 64, HH, BB), 128>>>(data, bias, out);
}

// round 9
// speedup vs baseline: 1.5599x; 1.5599x over previous
#include <cuda_runtime.h>
#include <math.h>
#include <stdint.h>

#define HH 128
#define WW 128
#define BB 8
#define CIN 64
#define COUT 64
#define HW (HH*WW)
#define NCH 27            // 18 offset channels + 9 mask channels
#define CSTR 68           // colT row stride in floats

// scratch (allocation-free: device globals)
__device__ float g_om[BB*NCH*HW];     // offsets + mask=2*sigmoid
__device__ float g_wT[9*64*64];       // [tap][cin][oc]

// ---------------------------------------------------------------------------
// packed fp32x2 helpers
// ---------------------------------------------------------------------------
__device__ __forceinline__ uint64_t pack2(float lo, float hi) {
    uint64_t r;
    asm("mov.b64 %0, {%1,%2};" : "=l"(r)
        : "r"(__float_as_uint(lo)), "r"(__float_as_uint(hi)));
    return r;
}
__device__ __forceinline__ void unpack2(uint64_t v, float& lo, float& hi) {
    uint32_t a, b;
    asm("mov.b64 {%0,%1}, %2;" : "=r"(a), "=r"(b) : "l"(v));
    lo = __uint_as_float(a); hi = __uint_as_float(b);
}
#define FFMA2(acc, a, b) \
    asm("fma.rn.f32x2 %0, %1, %2, %0;" : "+l"(acc) : "l"(a), "l"(b))

// ---------------------------------------------------------------------------
// Kernel 0: weight transform [oc][c][3][3] -> g_wT[t][c][oc]
// ---------------------------------------------------------------------------
__global__ void transpose_w_kernel(const float* __restrict__ w) {
    int idx = blockIdx.x * 256 + threadIdx.x;
    if (idx < 576 * COUT) {
        int oc  = idx / 576;
        int rem = idx % 576;
        int c   = rem / 9;
        int t   = rem % 9;
        g_wT[t * 4096 + c * 64 + oc] = w[idx];
    }
}

// ---------------------------------------------------------------------------
// Kernel 1: fused 3x3 conv -> 18 offsets + 9 masks (2*sigmoid).
// 4 output rows per block (amortizes weight LDS over 2x FMA);
// oc-pairs split across blockIdx.z. grid = (H/4, B, 2).
// ---------------------------------------------------------------------------
#define NPAIR 7

__global__ void __launch_bounds__(128, 4) conv_offmask_kernel(
    const float* __restrict__ data,
    const float* __restrict__ w_off, const float* __restrict__ b_off,
    const float* __restrict__ w_mod, const float* __restrict__ b_mod)
{
    __shared__ uint64_t wsp[NPAIR * 32 * 10];       // 17920 B
    __shared__ float    dtile[8 * 6 * 132];         // 25344 B

    const int h0 = blockIdx.x * 4;
    const int b  = blockIdx.y;
    const int pb = blockIdx.z * NPAIR;              // pair base (0 or 7)
    const int x  = threadIdx.x;

    // zero halo columns (cells 0 and 129 of each of 8ch x 6 rows)
    if (threadIdx.x < 96) {
        int q = threadIdx.x / 12;
        int r = (threadIdx.x % 12) >> 1;
        int s = threadIdx.x & 1;
        dtile[q * 792 + r * 132 + s * 129] = 0.0f;
    }

    uint64_t acc2[4][NPAIR];
#pragma unroll
    for (int p = 0; p < NPAIR; p++) {
        int ocA = 2 * (pb + p), ocB = ocA + 1;
        float bA = (ocA < 18) ? b_off[ocA] : b_mod[ocA - 18];
        float bB = (ocB < 18) ? b_off[ocB] : ((ocB < 27) ? b_mod[ocB - 18] : 0.0f);
        acc2[0][p] = pack2(bA, bB);
        acc2[1][p] = acc2[0][p];
        acc2[2][p] = acc2[0][p];
        acc2[3][p] = acc2[0][p];
    }

    for (int c0 = 0; c0 < CIN; c0 += 32) {
        __syncthreads();
        // stage paired weights for this 32-channel chunk (this z's pairs)
        for (int idx = threadIdx.x; idx < NPAIR * 32 * 9; idx += 128) {
            int p  = idx / 288;
            int r  = idx % 288;
            int cc = r / 9;
            int k  = r % 9;
            int ocA = 2 * (pb + p), ocB = ocA + 1;
            const float* sA = (ocA < 18) ? (w_off + ocA * 576) : (w_mod + (ocA - 18) * 576);
            float vA = sA[(c0 + cc) * 9 + k];
            float vB = 0.0f;
            if (ocB < 27) {
                const float* sB = (ocB < 18) ? (w_off + ocB * 576) : (w_mod + (ocB - 18) * 576);
                vB = sB[(c0 + cc) * 9 + k];
            }
            wsp[(p * 32 + cc) * 10 + k] = pack2(vA, vB);
        }

        for (int cg = 0; cg < 4; cg++) {
            __syncthreads();
            const int cb = c0 + cg * 8;
            // stage 8 channels x 6 rows into smem (coalesced)
#pragma unroll
            for (int q = 0; q < 8; q++) {
                const float* dp = data + ((size_t)(b * CIN + cb + q)) * HW;
#pragma unroll
                for (int r = 0; r < 6; r++) {
                    int hy = h0 - 1 + r;
                    float v = 0.0f;
                    if (hy >= 0 && hy < HH) v = dp[hy * WW + x];
                    dtile[q * 792 + r * 132 + 1 + x] = v;
                }
            }
            __syncthreads();

#pragma unroll
            for (int q = 0; q < 8; q++) {
                const int cc = cg * 8 + q;
                const float* dp = dtile + q * 792 + x;
                uint64_t dup[6][3];
#pragma unroll
                for (int r = 0; r < 6; r++)
#pragma unroll
                    for (int kx = 0; kx < 3; kx++) {
                        float v = dp[r * 132 + kx];
                        dup[r][kx] = pack2(v, v);
                    }

#pragma unroll
                for (int p = 0; p < NPAIR; p++) {
                    const uint64_t* base = wsp + (p * 32 + cc) * 10;
                    ulonglong2 w01 = *(const ulonglong2*)(base + 0);
                    ulonglong2 w23 = *(const ulonglong2*)(base + 2);
                    ulonglong2 w45 = *(const ulonglong2*)(base + 4);
                    ulonglong2 w67 = *(const ulonglong2*)(base + 6);
                    uint64_t   w8  = base[8];
#pragma unroll
                    for (int rr = 0; rr < 4; rr++) {
                        FFMA2(acc2[rr][p], dup[rr + 0][0], w01.x);
                        FFMA2(acc2[rr][p], dup[rr + 0][1], w01.y);
                        FFMA2(acc2[rr][p], dup[rr + 0][2], w23.x);
                        FFMA2(acc2[rr][p], dup[rr + 1][0], w23.y);
                        FFMA2(acc2[rr][p], dup[rr + 1][1], w45.x);
                        FFMA2(acc2[rr][p], dup[rr + 1][2], w45.y);
                        FFMA2(acc2[rr][p], dup[rr + 2][0], w67.x);
                        FFMA2(acc2[rr][p], dup[rr + 2][1], w67.y);
                        FFMA2(acc2[rr][p], dup[rr + 2][2], w8);
                    }
                }
            }
        }
    }

#pragma unroll
    for (int rr = 0; rr < 4; rr++) {
        float* outp = g_om + ((size_t)(b * NCH) * HH + (h0 + rr)) * WW + x;
#pragma unroll
        for (int p = 0; p < NPAIR; p++) {
            float lo, hi;
            unpack2(acc2[rr][p], lo, hi);
            int ocA = 2 * (pb + p), ocB = ocA + 1;
            if (ocA >= 18) lo = 2.0f / (1.0f + expf(-lo));
            outp[ocA * HW] = lo;
            if (ocB < 27) {
                if (ocB >= 18) hi = 2.0f / (1.0f + expf(-hi));
                outp[ocB * HW] = hi;
            }
        }
    }
}

// ---------------------------------------------------------------------------
// Kernel 2: deform sample + GEMM (R6 pipelined version — best measured).
// gather for tap t+1 interleaved in 4 chunks with GEMM of tap t;
// wsm+colT double-buffered. smem 67.6KB -> 3 blocks/SM. grid = (W/64, H, B)
// ---------------------------------------------------------------------------
#define DSM_BYTES (2*16384 + 2*17408)   // 67584

__global__ void __launch_bounds__(128, 3) deform_main_kernel(
    const float* __restrict__ data,
    const float* __restrict__ bias,
    float* __restrict__ out)
{
    extern __shared__ char dsm[];
    float* wsmA = (float*)dsm;                 // 2 x 4096 floats
    float* colA = (float*)(dsm + 32768);       // 2 x 4352 floats (64*CSTR)

    const int w0  = blockIdx.x * 64;
    const int h   = blockIdx.y;
    const int b   = blockIdx.z;
    const int tid = threadIdx.x;

    const float* dbase = data + (size_t)b * CIN * HW;

    const int i   = tid >> 4;            // oc group
    const int j   = tid & 15;            // px group
    const int oc0 = i * 8;

    const int gp = tid & 63;             // gather pixel
    const int gc = (tid >> 6) * 32;      // gather channel base
    const int x  = w0 + gp;

    const float* omb = g_om + ((size_t)(b * NCH) * HH + h) * WW + x;

    uint64_t acc[4][4];
#pragma unroll
    for (int p = 0; p < 4; p++)
#pragma unroll
        for (int q = 0; q < 4; q++) acc[p][q] = 0ULL;

    auto compute_meta = [&](int t, float dy, float dx, float mk,
                            float& w00, float& w01, float& w10, float& w11,
                            int& i00, int& i01, int& i10, int& i11) {
        const float py = (float)(h - 1 + t / 3) + dy;
        const float px = (float)(x - 1 + t % 3) + dx;
        const float y0f = floorf(py), x0f = floorf(px);
        const float wy1 = py - y0f,  wx1 = px - x0f;
        const float wy0 = 1.0f - wy1, wx0 = 1.0f - wx1;
        const int y0 = (int)y0f, x0 = (int)x0f;
        const int y1 = y0 + 1,   x1 = x0 + 1;
        const bool vy0 = (y0 >= 0) && (y0 < HH);
        const bool vy1 = (y1 >= 0) && (y1 < HH);
        const bool vx0 = (x0 >= 0) && (x0 < WW);
        const bool vx1 = (x1 >= 0) && (x1 < WW);
        w00 = (vy0 && vx0) ? mk * wy0 * wx0 : 0.0f;
        w01 = (vy0 && vx1) ? mk * wy0 * wx1 : 0.0f;
        w10 = (vy1 && vx0) ? mk * wy1 * wx0 : 0.0f;
        w11 = (vy1 && vx1) ? mk * wy1 * wx1 : 0.0f;
        const int yc0 = min(max(y0, 0), HH - 1);
        const int yc1 = min(max(y1, 0), HH - 1);
        const int xc0 = min(max(x0, 0), WW - 1);
        const int xc1 = min(max(x1, 0), WW - 1);
        i00 = yc0 * WW + xc0;
        i01 = yc0 * WW + xc1;
        i10 = yc1 * WW + xc0;
        i11 = yc1 * WW + xc1;
    };

    // ---- prologue: tap 0 staged unpipelined ----
    {
        float dyC = omb[0], dxC = omb[HW], mkC = omb[18 * HW];
        const float4* wsrc = (const float4*)g_wT;
        float4* wdst = (float4*)wsmA;
#pragma unroll
        for (int r = 0; r < 8; r++) wdst[tid + r * 128] = wsrc[tid + r * 128];

        float w00, w01, w10, w11; int i00, i01, i10, i11;
        compute_meta(0, dyC, dxC, mkC, w00, w01, w10, w11, i00, i01, i10, i11);
        const float* d2 = dbase + (size_t)gc * HW;
        float* cp = colA + gc * CSTR + gp;
#pragma unroll 8
        for (int cc = 0; cc < 32; cc++) {
            float v = w00 * d2[i00];
            v = fmaf(w01, d2[i01], v);
            v = fmaf(w10, d2[i10], v);
            v = fmaf(w11, d2[i11], v);
            cp[cc * CSTR] = v;
            d2 += HW;
        }
    }
    float dyN = omb[2 * HW], dxN = omb[3 * HW], mkN = omb[19 * HW];
    __syncthreads();

    // ---- main pipelined loop ----
#pragma unroll 1
    for (int t = 0; t < 9; t++) {
        const int cur = t & 1, nxt = cur ^ 1;
        const bool more = (t < 8);

        float w00 = 0, w01 = 0, w10 = 0, w11 = 0;
        int i00 = 0, i01 = 0, i10 = 0, i11 = 0;
        if (more) {
            compute_meta(t + 1, dyN, dxN, mkN, w00, w01, w10, w11, i00, i01, i10, i11);
            if (t + 2 < 9) {
                dyN = omb[2 * (t + 2) * HW];
                dxN = omb[(2 * (t + 2) + 1) * HW];
                mkN = omb[(18 + t + 2) * HW];
            }
        }

        const float* wrow = wsmA + cur * 4096 + oc0;
        const float* crow = colA + cur * 4352 + j * 4;
        const float4* wsrc = (const float4*)(g_wT + (more ? (t + 1) : 0) * 4096);
        float4* wdst = (float4*)(wsmA + nxt * 4096);
        float* cpn = colA + nxt * 4352 + gc * CSTR + gp;

#pragma unroll 1
        for (int q = 0; q < 4; q++) {
            float4 wrA, wrB;
            float g[32];
            if (more) {
                wrA = wsrc[tid + (2 * q) * 128];
                wrB = wsrc[tid + (2 * q + 1) * 128];
                const float* dq = dbase + (size_t)(gc + q * 8) * HW;
#pragma unroll
                for (int cc = 0; cc < 8; cc++) {
                    g[4 * cc + 0] = dq[i00];
                    g[4 * cc + 1] = dq[i01];
                    g[4 * cc + 2] = dq[i10];
                    g[4 * cc + 3] = dq[i11];
                    dq += HW;
                }
            }

            const float* wk = wrow + q * 16 * 64;
            const float* ck = crow + q * 16 * CSTR;
#pragma unroll
            for (int kl = 0; kl < 16; kl++) {
                ulonglong2 wA = *(const ulonglong2*)(wk + kl * 64);
                ulonglong2 wB = *(const ulonglong2*)(wk + kl * 64 + 4);
                float4 cv = *(const float4*)(ck + kl * CSTR);
                uint64_t c0 = pack2(cv.x, cv.x);
                uint64_t c1 = pack2(cv.y, cv.y);
                uint64_t c2 = pack2(cv.z, cv.z);
                uint64_t c3 = pack2(cv.w, cv.w);
                FFMA2(acc[0][0], wA.x, c0); FFMA2(acc[0][1], wA.x, c1);
                FFMA2(acc[0][2], wA.x, c2); FFMA2(acc[0][3], wA.x, c3);
                FFMA2(acc[1][0], wA.y, c0); FFMA2(acc[1][1], wA.y, c1);
                FFMA2(acc[1][2], wA.y, c2); FFMA2(acc[1][3], wA.y, c3);
                FFMA2(acc[2][0], wB.x, c0); FFMA2(acc[2][1], wB.x, c1);
                FFMA2(acc[2][2], wB.x, c2); FFMA2(acc[2][3], wB.x, c3);
                FFMA2(acc[3][0], wB.y, c0); FFMA2(acc[3][1], wB.y, c1);
                FFMA2(acc[3][2], wB.y, c2); FFMA2(acc[3][3], wB.y, c3);
            }

            if (more) {
                wdst[tid + (2 * q) * 128] = wrA;
                wdst[tid + (2 * q + 1) * 128] = wrB;
#pragma unroll
                for (int cc = 0; cc < 8; cc++) {
                    float v = w00 * g[4 * cc + 0];
                    v = fmaf(w01, g[4 * cc + 1], v);
                    v = fmaf(w10, g[4 * cc + 2], v);
                    v = fmaf(w11, g[4 * cc + 3], v);
                    cpn[(q * 8 + cc) * CSTR] = v;
                }
            }
        }
        __syncthreads();
    }

    // ---- epilogue: bias + relu + float4 stores ----
#pragma unroll
    for (int p = 0; p < 4; p++) {
        const int ocA = oc0 + 2 * p;
        const float bA = bias[ocA];
        const float bB = bias[ocA + 1];
        float a0, b0, a1, b1, a2, b2, a3, b3;
        unpack2(acc[p][0], a0, b0);
        unpack2(acc[p][1], a1, b1);
        unpack2(acc[p][2], a2, b2);
        unpack2(acc[p][3], a3, b3);
        float* obA = out + (((size_t)(b * COUT + ocA)) * HH + h) * WW + w0 + j * 4;
        float4 rA = make_float4(fmaxf(a0 + bA, 0.f), fmaxf(a1 + bA, 0.f),
                                fmaxf(a2 + bA, 0.f), fmaxf(a3 + bA, 0.f));
        *(float4*)obA = rA;
        float4 rB = make_float4(fmaxf(b0 + bB, 0.f), fmaxf(b1 + bB, 0.f),
                                fmaxf(b2 + bB, 0.f), fmaxf(b3 + bB, 0.f));
        *(float4*)(obA + HW) = rB;
    }
}

// ---------------------------------------------------------------------------
extern "C" void kernel_launch(void* const* d_in, const int* in_sizes, int n_in,
                              void* d_out, int out_size)
{
    const float* data  = (const float*)d_in[0];
    const float* w     = (const float*)d_in[1];
    const float* bias  = (const float*)d_in[2];
    const float* w_off = (const float*)d_in[3];
    const float* b_off = (const float*)d_in[4];
    const float* w_mod = (const float*)d_in[5];
    const float* b_mod = (const float*)d_in[6];
    float* out = (float*)d_out;

    cudaFuncSetAttribute(deform_main_kernel,
                         cudaFuncAttributeMaxDynamicSharedMemorySize, DSM_BYTES);

    conv_offmask_kernel<<<dim3(HH / 4, BB, 2), 128>>>(data, w_off, b_off, w_mod, b_mod);
    transpose_w_kernel<<<144, 256>>>(w);
    deform_main_kernel<<<dim3(WW / 64, HH, BB), 128, DSM_BYTES>>>(data, bias, out);
}